// round 12
// baseline (speedup 1.0000x reference)
#include <cuda_runtime.h>

#define NN     65536
#define VOCAB  1000
#define DIM    256
#define DIM3   768
#define TB     16                 // fat-path nodes per batch
#define PAD    20
#define TPB    256
#define EMBB   (VOCAB / 4)        // 250 embproj blocks
#define DEPB   (2 * NN / 256)     // 512 prep blocks

// ---------------- scratch (static device allocations only) ----------------
static __device__ float g_hsum [2 * NN * DIM];    // child h sums   (134 MB)
static __device__ float g_fcsum[2 * NN * DIM];    // child f*c sums (134 MB)
static __device__ float g_embp_iou[VOCAB * DIM3]; // emb@Wioux + bioux + biouh
static __device__ float g_embp_fx [VOCAB * DIM];  // emb@Wfx   + bfx   + bfh
static __device__ float g_leaf_c  [VOCAB * DIM];
static __device__ float g_leaf_h  [VOCAB * DIM];
static __device__ float g_fpreL   [VOCAB * DIM];  // leaf_h @ Wfh per token
static __device__ int   g_par  [2 * NN];
static __device__ int   g_tok  [2 * NN];
static __device__ int   g_mark [2 * NN];          // 1 = internal node
static __device__ int   g_pend [2 * NN];          // children not yet completed
static __device__ int   g_qbuf [2 * NN];          // work queue (init -1)
static __device__ int   g_qtail;                  // reserve counter
static __device__ int   g_qhead;                  // consume counter
static __device__ int   g_total;                  // total internal nodes
static __device__ float g_croot[2 * DIM];

__device__ __forceinline__ float sigm(float x) { return 1.0f / (1.0f + expf(-x)); }

// ---- f32x2 helpers (sm_100+; ptxas never auto-fuses FFMA2 from C++) ----
__device__ __forceinline__ unsigned long long pack2(float lo, float hi) {
  unsigned long long r;
  asm("mov.b64 %0, {%1, %2};" : "=l"(r) : "f"(lo), "f"(hi));
  return r;
}
__device__ __forceinline__ void unpack2(unsigned long long v, float& lo, float& hi) {
  asm("mov.b64 {%0, %1}, %2;" : "=f"(lo), "=f"(hi) : "l"(v));
}
#define FMA2(d, h, w) asm("fma.rn.f32x2 %0, %1, %2, %0;" : "+l"(d) : "l"(h), "l"(w))

// ---------------- phase 1 (FUSED): embedding projections  ∥  parent/childcnt ----------------
__global__ void k_prep(const float* __restrict__ emb,
                       const float* __restrict__ Wioux, const float* __restrict__ bioux,
                       const float* __restrict__ biouh,
                       const float* __restrict__ Wfx,   const float* __restrict__ bfx,
                       const float* __restrict__ bfh,
                       const float* __restrict__ Wfh,
                       const int* __restrict__ lpar, const int* __restrict__ rpar,
                       const int* __restrict__ ltok, const int* __restrict__ rtok) {
  const int t = threadIdx.x;
  if (blockIdx.x < EMBB) {
    __shared__ float xs[4][DIM];
    const int v0 = blockIdx.x * 4;
    #pragma unroll
    for (int j = 0; j < 4; ++j) xs[j][t] = emb[(v0 + j) * DIM + t];
    __syncthreads();

    const float b0 = bioux[t]           + biouh[t];
    const float b1 = bioux[DIM + t]     + biouh[DIM + t];
    const float b2 = bioux[2*DIM + t]   + biouh[2*DIM + t];
    const float bf = bfx[t] + bfh[t];
    float a0[4], a1[4], a2[4], af[4];
    #pragma unroll
    for (int j = 0; j < 4; ++j) { a0[j] = b0; a1[j] = b1; a2[j] = b2; af[j] = bf; }

    #pragma unroll 4
    for (int k = 0; k < DIM; ++k) {
      const float w0 = Wioux[k*DIM3 + t];
      const float w1 = Wioux[k*DIM3 + DIM + t];
      const float w2 = Wioux[k*DIM3 + 2*DIM + t];
      const float wf = Wfx  [k*DIM + t];
      #pragma unroll
      for (int j = 0; j < 4; ++j) {
        const float xv = xs[j][k];
        a0[j] = fmaf(xv, w0, a0[j]);
        a1[j] = fmaf(xv, w1, a1[j]);
        a2[j] = fmaf(xv, w2, a2[j]);
        af[j] = fmaf(xv, wf, af[j]);
      }
    }

    float hj[4];
    #pragma unroll
    for (int j = 0; j < 4; ++j) {
      const int v = v0 + j;
      g_embp_iou[v*DIM3 + t]         = a0[j];
      g_embp_iou[v*DIM3 + DIM + t]   = a1[j];
      g_embp_iou[v*DIM3 + 2*DIM + t] = a2[j];
      g_embp_fx [v*DIM + t]          = af[j];
      const float c = sigm(a0[j]) * tanhf(a2[j]);
      const float h = sigm(a1[j]) * tanhf(c);
      g_leaf_c[v*DIM + t] = c;
      g_leaf_h[v*DIM + t] = h;
      hj[j] = h;
    }
    __syncthreads();
    #pragma unroll
    for (int j = 0; j < 4; ++j) xs[j][t] = hj[j];
    __syncthreads();

    float fp[4] = {0.f, 0.f, 0.f, 0.f};
    #pragma unroll 4
    for (int k = 0; k < DIM; ++k) {
      const float wf = Wfh[k*DIM + t];
      #pragma unroll
      for (int j = 0; j < 4; ++j) fp[j] = fmaf(xs[j][k], wf, fp[j]);
    }
    #pragma unroll
    for (int j = 0; j < 4; ++j) g_fpreL[(v0 + j)*DIM + t] = fp[j];
  } else {
    const int g = (blockIdx.x - EMBB) * 256 + t;
    const int tree = g >> 16, node = g & (NN - 1);
    const int* par = tree ? rpar : lpar;
    const int* tok = tree ? rtok : ltok;
    g_par[g] = (tree << 16) | par[node];
    g_tok[g] = tok[node];
    if (node != 0) {
      const int pg = (tree << 16) | par[node];
      atomicAdd(&g_pend[pg], 1);                       // childcnt
      if (atomicExch(&g_mark[pg], 1) == 0)
        atomicAdd(&g_total, 1);                        // count internal nodes
    }
  }
}

// ---------------- phase 2: bulk leaf pass + queue seeding ----------------
// Leaves contribute h / f*c to parents via atomics, then decrement the
// parent's pending counter; last child to finish enqueues the parent.
__global__ void k_leaf() {
  const int t = threadIdx.x;
  const int node = blockIdx.x * 4 + (t >> 6);
  const bool isleaf = (node < 2 * NN) && (g_mark[node] == 0);
  if (isleaf) {
    const int t4 = (t & 63) * 4;
    const int pg = g_par[node];
    const int v  = g_tok[node];
    const int pv = g_tok[pg];
    const float4 h4 = *(const float4*)&g_leaf_h [v  * DIM + t4];
    const float4 c4 = *(const float4*)&g_leaf_c [v  * DIM + t4];
    const float4 fp = *(const float4*)&g_fpreL  [v  * DIM + t4];
    const float4 fx = *(const float4*)&g_embp_fx[pv * DIM + t4];
    float* hs = &g_hsum [pg * DIM + t4];
    float* fc = &g_fcsum[pg * DIM + t4];
    atomicAdd(hs + 0, h4.x); atomicAdd(hs + 1, h4.y);
    atomicAdd(hs + 2, h4.z); atomicAdd(hs + 3, h4.w);
    atomicAdd(fc + 0, sigm(fp.x + fx.x) * c4.x);
    atomicAdd(fc + 1, sigm(fp.y + fx.y) * c4.y);
    atomicAdd(fc + 2, sigm(fp.z + fx.z) * c4.z);
    atomicAdd(fc + 3, sigm(fp.w + fx.w) * c4.w);
  }
  __threadfence();
  __syncthreads();
  if (isleaf && (t & 63) == 0) {
    const int pg = g_par[node];
    if (atomicSub(&g_pend[pg], 1) == 1) {
      const int slot = atomicAdd(&g_qtail, 1);
      atomicExch(&g_qbuf[slot], pg);                   // publish
    }
  }
}

// ---------------- phase 3: persistent dependency-driven worker ----------------
// Pops batches of up to 16 published nodes (CAS on head over published prefix —
// never waits on reserved-but-unpublished slots, so no deadlock).
// n>=4: fat 16-node f32x2 math (R9 config). n<4: per-node wide math.
__global__ void __launch_bounds__(TPB, 2) k_queue(const float* __restrict__ Wiouh,
                                                  const float* __restrict__ Wfh) {
  __shared__ __align__(16) union {
    struct { float hT[DIM][PAD]; float fcsh[TB][DIM]; } fat;                      // 36 KB
    struct { float hs[DIM]; float fc[DIM]; float hv[DIM]; float red[8][DIM3]; } wide; // 27 KB
  } sm;
  __shared__ int snode[TB], spar[TB], stok[TB], sptok[TB];
  __shared__ int sh_head, sh_stat, sh_pub[TB];
  const int t = threadIdx.x;
  const int w = t >> 5, l = t & 31;
  const int total = g_total;

  for (;;) {
    // ---------- pop a batch ----------
    int nb = 0, tries = 0, done = 0;
    for (;;) {
      __syncthreads();                       // also protects smem reuse from last batch
      if (t == 0) sh_head = atomicAdd(&g_qhead, 0);
      __syncthreads();
      const int head = sh_head;
      if (head >= total) { done = 1; break; }
      if (t < TB) sh_pub[t] = (head + t < total) ? (__ldcg(&g_qbuf[head + t]) >= 0) : 0;
      __syncthreads();
      if (t == 0) {
        int n = 0;
        while (n < TB && sh_pub[n]) n++;
        const int remaining = total - head;
        if (n == 0) { __nanosleep(200); sh_stat = -1; }
        else if (n < TB && remaining > 4096 && tries < 4) { __nanosleep(200); sh_stat = -1; }
        else if (atomicCAS(&g_qhead, head, head + n) == head) sh_stat = n;
        else sh_stat = -1;
      }
      __syncthreads();
      ++tries;
      if (sh_stat > 0) {
        nb = sh_stat;
        if (t < TB) {
          const int gg = (t < nb) ? __ldcg(&g_qbuf[head + t]) : -1;
          snode[t] = gg;
          if (gg >= 0) {
            const int pg = g_par[gg];
            spar[t] = pg; stok[t] = g_tok[gg]; sptok[t] = g_tok[pg];
          }
        }
        break;
      }
    }
    if (done) break;
    __syncthreads();                         // snode/spar/stok visible

    if (nb >= 4) {
      // ---------- fat path: up to 16 nodes, f32x2 node pairs ----------
      #pragma unroll
      for (int b = 0; b < TB; ++b) {
        const int gg = snode[b];
        sm.fat.hT[t][b]   = (gg >= 0) ? __ldcg(&g_hsum [gg * DIM + t]) : 0.0f;
        sm.fat.fcsh[b][t] = (gg >= 0) ? __ldcg(&g_fcsum[gg * DIM + t]) : 0.0f;
      }

      unsigned long long A0[8], A1[8], A2[8];
      #pragma unroll
      for (int p = 0; p < 8; ++p) {
        float e00 = 0.f, e01 = 0.f, e10 = 0.f, e11 = 0.f, e20 = 0.f, e21 = 0.f;
        if (snode[2*p] >= 0) {
          const int tv = stok[2*p] * DIM3;
          e00 = g_embp_iou[tv + t]; e10 = g_embp_iou[tv + DIM + t]; e20 = g_embp_iou[tv + 2*DIM + t];
        }
        if (snode[2*p+1] >= 0) {
          const int tv = stok[2*p+1] * DIM3;
          e01 = g_embp_iou[tv + t]; e11 = g_embp_iou[tv + DIM + t]; e21 = g_embp_iou[tv + 2*DIM + t];
        }
        A0[p] = pack2(e00, e01); A1[p] = pack2(e10, e11); A2[p] = pack2(e20, e21);
      }
      __syncthreads();

      // mv1: thread t owns cols t, 256+t, 512+t
      #pragma unroll 4
      for (int k = 0; k < DIM; ++k) {
        const float* wr = Wiouh + k * DIM3 + t;
        const float w0 = __ldg(wr), w1 = __ldg(wr + DIM), w2 = __ldg(wr + 2*DIM);
        const unsigned long long W0 = pack2(w0, w0), W1 = pack2(w1, w1), W2 = pack2(w2, w2);
        const ulonglong2* hr = reinterpret_cast<const ulonglong2*>(&sm.fat.hT[k][0]);
        const ulonglong2 hA = hr[0], hB = hr[1], hC = hr[2], hD = hr[3];
        FMA2(A0[0], hA.x, W0); FMA2(A1[0], hA.x, W1); FMA2(A2[0], hA.x, W2);
        FMA2(A0[1], hA.y, W0); FMA2(A1[1], hA.y, W1); FMA2(A2[1], hA.y, W2);
        FMA2(A0[2], hB.x, W0); FMA2(A1[2], hB.x, W1); FMA2(A2[2], hB.x, W2);
        FMA2(A0[3], hB.y, W0); FMA2(A1[3], hB.y, W1); FMA2(A2[3], hB.y, W2);
        FMA2(A0[4], hC.x, W0); FMA2(A1[4], hC.x, W1); FMA2(A2[4], hC.x, W2);
        FMA2(A0[5], hC.y, W0); FMA2(A1[5], hC.y, W1); FMA2(A2[5], hC.y, W2);
        FMA2(A0[6], hD.x, W0); FMA2(A1[6], hD.x, W1); FMA2(A2[6], hD.x, W2);
        FMA2(A0[7], hD.y, W0); FMA2(A1[7], hD.y, W1); FMA2(A2[7], hD.y, W2);
      }

      // gates: cc -> fcsh (same-thread overwrite), hh in regs
      float hh[TB];
      #pragma unroll
      for (int p = 0; p < 8; ++p) {
        float a0l, a0h, a1l, a1h, a2l, a2h;
        unpack2(A0[p], a0l, a0h);
        unpack2(A1[p], a1l, a1h);
        unpack2(A2[p], a2l, a2h);
        {
          const int b = 2*p;
          const float c = sigm(a0l) * tanhf(a2l) + sm.fat.fcsh[b][t];
          hh[b] = sigm(a1l) * tanhf(c);
          sm.fat.fcsh[b][t] = c;
        }
        {
          const int b = 2*p + 1;
          const float c = sigm(a0h) * tanhf(a2h) + sm.fat.fcsh[b][t];
          hh[b] = sigm(a1h) * tanhf(c);
          sm.fat.fcsh[b][t] = c;
        }
      }
      __syncthreads();
      #pragma unroll
      for (int b = 0; b < TB; ++b) sm.fat.hT[t][b] = hh[b];
      __syncthreads();

      // mv2: fpre = h @ Wfh + folded(embp_fx[parent_tok])
      unsigned long long F[8];
      #pragma unroll
      for (int p = 0; p < 8; ++p) {
        const float f0 = (snode[2*p]   >= 0) ? g_embp_fx[sptok[2*p]   * DIM + t] : 0.f;
        const float f1 = (snode[2*p+1] >= 0) ? g_embp_fx[sptok[2*p+1] * DIM + t] : 0.f;
        F[p] = pack2(f0, f1);
      }
      #pragma unroll 4
      for (int k = 0; k < DIM; ++k) {
        const float wf = __ldg(Wfh + k * DIM + t);
        const unsigned long long Wf = pack2(wf, wf);
        const ulonglong2* hr = reinterpret_cast<const ulonglong2*>(&sm.fat.hT[k][0]);
        const ulonglong2 hA = hr[0], hB = hr[1], hC = hr[2], hD = hr[3];
        FMA2(F[0], hA.x, Wf); FMA2(F[1], hA.y, Wf);
        FMA2(F[2], hB.x, Wf); FMA2(F[3], hB.y, Wf);
        FMA2(F[4], hC.x, Wf); FMA2(F[5], hC.y, Wf);
        FMA2(F[6], hD.x, Wf); FMA2(F[7], hD.y, Wf);
      }

      // epilogue: h from hT, c from fcsh
      #pragma unroll
      for (int p = 0; p < 8; ++p) {
        float fl, fh2;
        unpack2(F[p], fl, fh2);
        #pragma unroll
        for (int q = 0; q < 2; ++q) {
          const int b = 2*p + q;
          const int gg = snode[b];
          if (gg < 0) continue;
          const float fv = q ? fh2 : fl;
          const float hval = sm.fat.hT[t][b];
          const float cval = sm.fat.fcsh[b][t];
          if ((gg & (NN - 1)) == 0) {
            g_croot[(gg >> 16) * DIM + t] = cval;
          } else {
            atomicAdd(&g_hsum [spar[b] * DIM + t], hval);
            atomicAdd(&g_fcsum[spar[b] * DIM + t], sigm(fv) * cval);
          }
        }
      }

      // completion: decrement parents, enqueue newly-ready
      __threadfence();
      __syncthreads();
      if (t < nb) {
        const int gg = snode[t];
        if (gg >= 0 && (gg & (NN - 1)) != 0) {
          const int pg = spar[t];
          if (atomicSub(&g_pend[pg], 1) == 1) {
            const int slot = atomicAdd(&g_qtail, 1);
            atomicExch(&g_qbuf[slot], pg);
          }
        }
      }
    } else {
      // ---------- wide path: each node block-wide (k split by warp) ----------
      for (int bi = 0; bi < nb; ++bi) {
        const int gg = snode[bi];
        const int pg = spar[bi];
        const int tok = stok[bi], ptok = sptok[bi];
        sm.wide.hs[t] = __ldcg(&g_hsum [gg * DIM + t]);
        sm.wide.fc[t] = __ldcg(&g_fcsum[gg * DIM + t]);
        __syncthreads();

        {
          const int k0 = w << 5;
          #pragma unroll 2
          for (int j = 0; j < 24; ++j) {
            float p = 0.f;
            const float* col = Wiouh + k0 * DIM3 + l + 32*j;
            #pragma unroll
            for (int kk = 0; kk < 32; ++kk)
              p = fmaf(sm.wide.hs[k0 + kk], __ldg(col + kk * DIM3), p);
            sm.wide.red[w][l + 32*j] = p;
          }
        }
        __syncthreads();

        float i0 = 0.f, o0 = 0.f, u0 = 0.f;
        #pragma unroll
        for (int w2 = 0; w2 < 8; ++w2) {
          i0 += sm.wide.red[w2][t];
          o0 += sm.wide.red[w2][DIM + t];
          u0 += sm.wide.red[w2][2*DIM + t];
        }
        const int tv = tok * DIM3;
        i0 += g_embp_iou[tv + t];
        o0 += g_embp_iou[tv + DIM + t];
        u0 += g_embp_iou[tv + 2*DIM + t];
        const float cval = sigm(i0) * tanhf(u0) + sm.wide.fc[t];
        const float hval = sigm(o0) * tanhf(cval);
        __syncthreads();
        sm.wide.hv[t] = hval;
        __syncthreads();

        {
          const int k0 = w << 5;
          #pragma unroll 2
          for (int j = 0; j < 8; ++j) {
            float p = 0.f;
            const float* col = Wfh + k0 * DIM + l + 32*j;
            #pragma unroll
            for (int kk = 0; kk < 32; ++kk)
              p = fmaf(sm.wide.hv[k0 + kk], __ldg(col + kk * DIM), p);
            sm.wide.red[w][l + 32*j] = p;
          }
        }
        __syncthreads();

        float f = g_embp_fx[ptok * DIM + t];
        #pragma unroll
        for (int w2 = 0; w2 < 8; ++w2) f += sm.wide.red[w2][t];

        if ((gg & (NN - 1)) == 0) {
          g_croot[(gg >> 16) * DIM + t] = cval;
        } else {
          atomicAdd(&g_hsum [pg * DIM + t], hval);
          atomicAdd(&g_fcsum[pg * DIM + t], sigm(f) * cval);
        }

        __threadfence();
        __syncthreads();
        if (t == 0 && (gg & (NN - 1)) != 0) {
          if (atomicSub(&g_pend[pg], 1) == 1) {
            const int slot = atomicAdd(&g_qtail, 1);
            atomicExch(&g_qbuf[slot], pg);
          }
        }
        __syncthreads();
      }
    }
  }
}

// ---------------- phase 4: similarity head ----------------
__global__ void k_head(const float* __restrict__ Wh, const float* __restrict__ bh,
                       const float* __restrict__ Wp, const float* __restrict__ bp,
                       float* __restrict__ out) {
  __shared__ float vec[2 * DIM];
  __shared__ float s0[DIM], s1[DIM];
  const int t = threadIdx.x;
  const float cl = g_croot[t], cr = g_croot[DIM + t];
  vec[t] = cl * cr;
  vec[DIM + t] = fabsf(cl - cr);
  __syncthreads();
  float acc = bh[t];
  #pragma unroll 4
  for (int k = 0; k < 2 * DIM; ++k) acc = fmaf(vec[k], Wh[k * DIM + t], acc);
  const float hid = sigm(acc);
  s0[t] = hid * Wp[t * 2 + 0];
  s1[t] = hid * Wp[t * 2 + 1];
  __syncthreads();
  for (int s = DIM / 2; s > 0; s >>= 1) {
    if (t < s) { s0[t] += s0[t + s]; s1[t] += s1[t + s]; }
    __syncthreads();
  }
  if (t == 0) {
    const float l0 = s0[0] + bp[0], l1 = s1[0] + bp[1];
    const float m = fmaxf(l0, l1);
    const float e0 = expf(l0 - m), e1 = expf(l1 - m);
    const float inv = 1.0f / (e0 + e1);
    out[0] = e0 * inv;
    out[1] = e1 * inv;
  }
}

// ---------------- launcher (graph-capturable) ----------------
extern "C" void kernel_launch(void* const* d_in, const int* in_sizes, int n_in,
                              void* d_out, int out_size) {
  (void)in_sizes; (void)n_in;
  const int*   l_tok = (const int*)  d_in[0];
  const int*   l_par = (const int*)  d_in[1];
  const int*   r_tok = (const int*)  d_in[2];
  const int*   r_par = (const int*)  d_in[3];
  const float* emb   = (const float*)d_in[4];
  const float* Wioux = (const float*)d_in[5];
  const float* bioux = (const float*)d_in[6];
  const float* Wiouh = (const float*)d_in[7];
  const float* biouh = (const float*)d_in[8];
  const float* Wfx   = (const float*)d_in[9];
  const float* bfx   = (const float*)d_in[10];
  const float* Wfh   = (const float*)d_in[11];
  const float* bfh   = (const float*)d_in[12];
  const float* Wh    = (const float*)d_in[13];
  const float* bh    = (const float*)d_in[14];
  const float* Wp    = (const float*)d_in[15];
  const float* bp    = (const float*)d_in[16];
  float* out = (float*)d_out;
  (void)out_size;

  void *p_hs, *p_fc, *p_mk, *p_pd, *p_qb, *p_qt, *p_qh, *p_tt;
  cudaGetSymbolAddress(&p_hs, g_hsum);
  cudaGetSymbolAddress(&p_fc, g_fcsum);
  cudaGetSymbolAddress(&p_mk, g_mark);
  cudaGetSymbolAddress(&p_pd, g_pend);
  cudaGetSymbolAddress(&p_qb, g_qbuf);
  cudaGetSymbolAddress(&p_qt, g_qtail);
  cudaGetSymbolAddress(&p_qh, g_qhead);
  cudaGetSymbolAddress(&p_tt, g_total);
  cudaMemsetAsync(p_hs, 0,    sizeof(float) * 2ull * NN * DIM);
  cudaMemsetAsync(p_fc, 0,    sizeof(float) * 2ull * NN * DIM);
  cudaMemsetAsync(p_mk, 0,    sizeof(int) * 2 * NN);
  cudaMemsetAsync(p_pd, 0,    sizeof(int) * 2 * NN);
  cudaMemsetAsync(p_qb, 0xFF, sizeof(int) * 2 * NN);   // -1 = unpublished
  cudaMemsetAsync(p_qt, 0,    sizeof(int));
  cudaMemsetAsync(p_qh, 0,    sizeof(int));
  cudaMemsetAsync(p_tt, 0,    sizeof(int));

  k_prep<<<EMBB + DEPB, 256>>>(emb, Wioux, bioux, biouh, Wfx, bfx, bfh, Wfh,
                               l_par, r_par, l_tok, r_tok);
  k_leaf<<<(2 * NN + 3) / 4, 256>>>();

  int dev = 0;
  cudaGetDevice(&dev);
  int sms = 148;
  cudaDeviceGetAttribute(&sms, cudaDevAttrMultiProcessorCount, dev);
  int maxb = 1;
  cudaOccupancyMaxActiveBlocksPerMultiprocessor(&maxb, k_queue, TPB, 0);
  if (maxb > 2) maxb = 2;
  if (maxb < 1) maxb = 1;
  k_queue<<<sms * maxb, TPB>>>(Wiouh, Wfh);   // no grid barrier: safe at any residency

  k_head<<<1, DIM>>>(Wh, bh, Wp, bp, out);
}

// round 13
// speedup vs baseline: 1.8954x; 1.8954x over previous
#include <cuda_runtime.h>

#define NN     65536
#define VOCAB  1000
#define DIM    256
#define DIM3   768
#define MAXLV  192
#define TB     16                 // fat-path nodes per chunk
#define PAD    20
#define WTHR   64                 // wide-path level-size threshold
#define EMBB   (VOCAB / 4)        // 250 embproj blocks
#define DEPB   (2 * NN / 256)     // 512 depth blocks

// ---------------- scratch (static device allocations only) ----------------
static __device__ float g_hsum [2 * NN * DIM];    // child h sums   (134 MB)
static __device__ float g_fcsum[2 * NN * DIM];    // child f*c sums (134 MB)
static __device__ float g_embp_iou[VOCAB * DIM3]; // emb@Wioux + bioux + biouh
static __device__ float g_embp_fx [VOCAB * DIM];  // emb@Wfx   + bfx   + bfh
static __device__ float g_leaf_c  [VOCAB * DIM];
static __device__ float g_leaf_h  [VOCAB * DIM];
static __device__ float g_fpreL   [VOCAB * DIM];  // leaf_h @ Wfh per token
static __device__ __align__(16) float2 g_W2iou[DIM * DIM3]; // Wiouh dup-packed {w,w}
static __device__ __align__(16) float2 g_W2fh [DIM * DIM];  // Wfh   dup-packed {w,w}
static __device__ int   g_sched[2 * NN];
static __device__ int   g_par  [2 * NN];
static __device__ int   g_tok  [2 * NN];
static __device__ int   g_depth[2 * NN];
static __device__ int   g_mark [2 * NN];          // 1 = internal node
static __device__ int   g_cnt  [2 * MAXLV];
static __device__ int   g_cur  [2 * MAXLV];
static __device__ int   g_start[2 * MAXLV];
static __device__ int   g_lo[MAXLV];
static __device__ int   g_hi[MAXLV];
static __device__ float g_croot[2 * DIM];
static __device__ unsigned g_barcnt;
static __device__ unsigned g_bargen;

__device__ __forceinline__ float sigm(float x) { return 1.0f / (1.0f + expf(-x)); }

// ---- f32x2 helpers (sm_100+; ptxas never auto-fuses FFMA2 from C++) ----
__device__ __forceinline__ unsigned long long pack2(float lo, float hi) {
  unsigned long long r;
  asm("mov.b64 %0, {%1, %2};" : "=l"(r) : "f"(lo), "f"(hi));
  return r;
}
__device__ __forceinline__ void unpack2(unsigned long long v, float& lo, float& hi) {
  asm("mov.b64 {%0, %1}, %2;" : "=f"(lo), "=f"(hi) : "l"(v));
}
#define FMA2(d, h, w) asm("fma.rn.f32x2 %0, %1, %2, %0;" : "+l"(d) : "l"(h), "l"(w))

// ---------------- phase 1 (FUSED): embedding projections  ∥  depth+hist ----------------
__global__ void k_prep(const float* __restrict__ emb,
                       const float* __restrict__ Wioux, const float* __restrict__ bioux,
                       const float* __restrict__ biouh,
                       const float* __restrict__ Wfx,   const float* __restrict__ bfx,
                       const float* __restrict__ bfh,
                       const float* __restrict__ Wfh,
                       const int* __restrict__ lpar, const int* __restrict__ rpar,
                       const int* __restrict__ ltok, const int* __restrict__ rtok) {
  const int t = threadIdx.x;
  if (blockIdx.x < EMBB) {
    __shared__ float xs[4][DIM];
    const int v0 = blockIdx.x * 4;
    #pragma unroll
    for (int j = 0; j < 4; ++j) xs[j][t] = emb[(v0 + j) * DIM + t];
    __syncthreads();

    const float b0 = bioux[t]           + biouh[t];
    const float b1 = bioux[DIM + t]     + biouh[DIM + t];
    const float b2 = bioux[2*DIM + t]   + biouh[2*DIM + t];
    const float bf = bfx[t] + bfh[t];
    float a0[4], a1[4], a2[4], af[4];
    #pragma unroll
    for (int j = 0; j < 4; ++j) { a0[j] = b0; a1[j] = b1; a2[j] = b2; af[j] = bf; }

    #pragma unroll 4
    for (int k = 0; k < DIM; ++k) {
      const float w0 = Wioux[k*DIM3 + t];
      const float w1 = Wioux[k*DIM3 + DIM + t];
      const float w2 = Wioux[k*DIM3 + 2*DIM + t];
      const float wf = Wfx  [k*DIM + t];
      #pragma unroll
      for (int j = 0; j < 4; ++j) {
        const float xv = xs[j][k];
        a0[j] = fmaf(xv, w0, a0[j]);
        a1[j] = fmaf(xv, w1, a1[j]);
        a2[j] = fmaf(xv, w2, a2[j]);
        af[j] = fmaf(xv, wf, af[j]);
      }
    }

    float hj[4];
    #pragma unroll
    for (int j = 0; j < 4; ++j) {
      const int v = v0 + j;
      g_embp_iou[v*DIM3 + t]         = a0[j];
      g_embp_iou[v*DIM3 + DIM + t]   = a1[j];
      g_embp_iou[v*DIM3 + 2*DIM + t] = a2[j];
      g_embp_fx [v*DIM + t]          = af[j];
      const float c = sigm(a0[j]) * tanhf(a2[j]);
      const float h = sigm(a1[j]) * tanhf(c);
      g_leaf_c[v*DIM + t] = c;
      g_leaf_h[v*DIM + t] = h;
      hj[j] = h;
    }
    __syncthreads();
    #pragma unroll
    for (int j = 0; j < 4; ++j) xs[j][t] = hj[j];
    __syncthreads();

    float fp[4] = {0.f, 0.f, 0.f, 0.f};
    #pragma unroll 4
    for (int k = 0; k < DIM; ++k) {
      const float wf = Wfh[k*DIM + t];
      #pragma unroll
      for (int j = 0; j < 4; ++j) fp[j] = fmaf(xs[j][k], wf, fp[j]);
    }
    #pragma unroll
    for (int j = 0; j < 4; ++j) g_fpreL[(v0 + j)*DIM + t] = fp[j];
  } else {
    const int g = (blockIdx.x - EMBB) * 256 + t;
    const int tree = g >> 16, node = g & (NN - 1);
    const int* par = tree ? rpar : lpar;
    const int* tok = tree ? rtok : ltok;
    int d = 0, i = node;
    while (i != 0) { i = par[i]; ++d; }
    if (d > MAXLV - 1) d = MAXLV - 1;
    g_depth[g] = d;
    g_par[g] = (tree << 16) | par[node];
    g_tok[g] = tok[node];
    if (node != 0) {
      const int pg = (tree << 16) | par[node];
      if (atomicExch(&g_mark[pg], 1) == 0)
        atomicAdd(&g_cnt[tree * MAXLV + (d - 1)], 1);
    }
  }
}

// ---------------- phase 1b: duplicate-pack weights as float2 {w,w} ----------------
__global__ void k_pack(const float* __restrict__ Wiouh, const float* __restrict__ Wfh) {
  const int i = blockIdx.x * blockDim.x + threadIdx.x;
  if (i < DIM * DIM3) {
    const float w = Wiouh[i];
    g_W2iou[i] = make_float2(w, w);
  }
  if (i < DIM * DIM) {
    const float w = Wfh[i];
    g_W2fh[i] = make_float2(w, w);
  }
}

// ---------------- phase 2: level offsets (smem-staged serial scan) ----------------
__global__ void k_scan() {
  __shared__ int c0[MAXLV], c1[MAXLV];
  const int t = threadIdx.x;
  if (t < MAXLV) { c0[t] = g_cnt[t]; c1[t] = g_cnt[MAXLV + t]; }
  __syncthreads();
  if (t == 0) {
    int off = 0;
    for (int L = MAXLV - 1; L >= 0; --L) {
      g_lo[L] = off;
      g_start[0 * MAXLV + L] = off; off += c0[L];
      g_start[1 * MAXLV + L] = off; off += c1[L];
      g_hi[L] = off;
    }
  }
}

// ---------------- phase 3 (FUSED): bucket internal nodes  ∥  bulk leaf pass ----------------
__global__ void k_scatlf() {
  const int t = threadIdx.x;
  if (blockIdx.x < DEPB) {
    const int g = blockIdx.x * 256 + t;
    if (g_mark[g] == 0) return;
    const int tree = g >> 16;
    const int d = g_depth[g];
    const int pos = g_start[tree * MAXLV + d] + atomicAdd(&g_cur[tree * MAXLV + d], 1);
    g_sched[pos] = g;
  } else {
    const int node = (blockIdx.x - DEPB) * 4 + (t >> 6);
    if (node >= 2 * NN) return;
    if (g_mark[node] != 0) return;
    const int t4 = (t & 63) * 4;
    const int pg = g_par[node];
    const int v  = g_tok[node];
    const int pv = g_tok[pg];
    const float4 h4 = *(const float4*)&g_leaf_h [v  * DIM + t4];
    const float4 c4 = *(const float4*)&g_leaf_c [v  * DIM + t4];
    const float4 fp = *(const float4*)&g_fpreL  [v  * DIM + t4];
    const float4 fx = *(const float4*)&g_embp_fx[pv * DIM + t4];
    float* hs = &g_hsum [pg * DIM + t4];
    float* fc = &g_fcsum[pg * DIM + t4];
    atomicAdd(hs + 0, h4.x); atomicAdd(hs + 1, h4.y);
    atomicAdd(hs + 2, h4.z); atomicAdd(hs + 3, h4.w);
    atomicAdd(fc + 0, sigm(fp.x + fx.x) * c4.x);
    atomicAdd(fc + 1, sigm(fp.y + fx.y) * c4.y);
    atomicAdd(fc + 2, sigm(fp.z + fx.z) * c4.z);
    atomicAdd(fc + 3, sigm(fp.w + fx.w) * c4.w);
  }
}

// ---------------- software grid barrier ----------------
__device__ __forceinline__ void gbar() {
  __threadfence();
  __syncthreads();
  if (threadIdx.x == 0) {
    volatile unsigned* vg = &g_bargen;
    const unsigned my = *vg;
    const unsigned tkt = atomicAdd(&g_barcnt, 1u);
    if (tkt == gridDim.x - 1) {
      g_barcnt = 0;
      __threadfence();
      atomicAdd(&g_bargen, 1u);
    } else {
      while (*vg == my) { __nanosleep(64); }
    }
    __threadfence();
  }
  __syncthreads();
}

// ---------------- phase 4: persistent wavefront ----------------
// Fat path (cnt > WTHR): 16-node chunks, f32x2 with dup-packed LDG.64 weights.
// Wide path (cnt <= WTHR): 1 node/block, k split across 8 warps.
__global__ void __launch_bounds__(256, 2) k_levels(const float* __restrict__ Wiouh,
                                                   const float* __restrict__ Wfh) {
  __shared__ __align__(16) union {
    struct { float hT[DIM][PAD]; float fcsh[TB][DIM]; } fat;                      // 36 KB
    struct { float hs[DIM]; float fc[DIM]; float hv[DIM]; float red[8][DIM3]; } wide; // 27 KB
  } sm;
  __shared__ int snode[TB], spar[TB], stok[TB], sptok[TB];
  const int t = threadIdx.x;
  const int w = t >> 5, l = t & 31;

  for (int L = MAXLV - 1; L >= 0; --L) {
    const int lo = g_lo[L], hi = g_hi[L];
    const int cnt = hi - lo;
    if (cnt == 0) continue;                  // identical on all blocks

    if (cnt <= WTHR) {
      // ---------- wide path: node-per-block, k split by warp ----------
      for (int idx = lo + (int)blockIdx.x; idx < hi; idx += gridDim.x) {
        const int gg = g_sched[idx];
        const int pg = g_par[gg];
        const int tok = g_tok[gg], ptok = g_tok[pg];
        sm.wide.hs[t] = __ldcg(&g_hsum [gg * DIM + t]);
        sm.wide.fc[t] = __ldcg(&g_fcsum[gg * DIM + t]);
        __syncthreads();

        {
          const int k0 = w << 5;
          #pragma unroll 2
          for (int j = 0; j < 24; ++j) {
            float p = 0.f;
            const float* col = Wiouh + k0 * DIM3 + l + 32*j;
            #pragma unroll
            for (int kk = 0; kk < 32; ++kk)
              p = fmaf(sm.wide.hs[k0 + kk], __ldg(col + kk * DIM3), p);
            sm.wide.red[w][l + 32*j] = p;
          }
        }
        __syncthreads();

        float i0 = 0.f, o0 = 0.f, u0 = 0.f;
        #pragma unroll
        for (int w2 = 0; w2 < 8; ++w2) {
          i0 += sm.wide.red[w2][t];
          o0 += sm.wide.red[w2][DIM + t];
          u0 += sm.wide.red[w2][2*DIM + t];
        }
        const int tv = tok * DIM3;
        i0 += g_embp_iou[tv + t];
        o0 += g_embp_iou[tv + DIM + t];
        u0 += g_embp_iou[tv + 2*DIM + t];
        const float cval = sigm(i0) * tanhf(u0) + sm.wide.fc[t];
        const float hval = sigm(o0) * tanhf(cval);
        __syncthreads();
        sm.wide.hv[t] = hval;
        __syncthreads();

        {
          const int k0 = w << 5;
          #pragma unroll 2
          for (int j = 0; j < 8; ++j) {
            float p = 0.f;
            const float* col = Wfh + k0 * DIM + l + 32*j;
            #pragma unroll
            for (int kk = 0; kk < 32; ++kk)
              p = fmaf(sm.wide.hv[k0 + kk], __ldg(col + kk * DIM), p);
            sm.wide.red[w][l + 32*j] = p;
          }
        }
        __syncthreads();

        float f = g_embp_fx[ptok * DIM + t];
        #pragma unroll
        for (int w2 = 0; w2 < 8; ++w2) f += sm.wide.red[w2][t];

        if ((gg & (NN - 1)) == 0) {
          g_croot[(gg >> 16) * DIM + t] = cval;
        } else {
          atomicAdd(&g_hsum [pg * DIM + t], hval);
          atomicAdd(&g_fcsum[pg * DIM + t], sigm(f) * cval);
        }
        __syncthreads();
      }
    } else {
      // ---------- fat path: 16-node chunks, f32x2, dup-packed weights ----------
      const int nch = (cnt + TB - 1) / TB;
      for (int ch = blockIdx.x; ch < nch; ch += gridDim.x) {
        const int base = lo + ch * TB;
        __syncthreads();                 // previous chunk done with shared

        if (t < TB) {
          const int gg = (base + t < hi) ? g_sched[base + t] : -1;
          snode[t] = gg;
          if (gg >= 0) {
            const int pg = g_par[gg];
            spar[t] = pg; stok[t] = g_tok[gg]; sptok[t] = g_tok[pg];
          }
        }
        __syncthreads();

        #pragma unroll
        for (int b = 0; b < TB; ++b) {
          const int gg = snode[b];
          sm.fat.hT[t][b]   = (gg >= 0) ? __ldcg(&g_hsum [gg * DIM + t]) : 0.0f;
          sm.fat.fcsh[b][t] = (gg >= 0) ? __ldcg(&g_fcsum[gg * DIM + t]) : 0.0f;
        }

        unsigned long long A0[8], A1[8], A2[8];
        #pragma unroll
        for (int p = 0; p < 8; ++p) {
          float e00 = 0.f, e01 = 0.f, e10 = 0.f, e11 = 0.f, e20 = 0.f, e21 = 0.f;
          if (snode[2*p] >= 0) {
            const int tv = stok[2*p] * DIM3;
            e00 = g_embp_iou[tv + t]; e10 = g_embp_iou[tv + DIM + t]; e20 = g_embp_iou[tv + 2*DIM + t];
          }
          if (snode[2*p+1] >= 0) {
            const int tv = stok[2*p+1] * DIM3;
            e01 = g_embp_iou[tv + t]; e11 = g_embp_iou[tv + DIM + t]; e21 = g_embp_iou[tv + 2*DIM + t];
          }
          A0[p] = pack2(e00, e01); A1[p] = pack2(e10, e11); A2[p] = pack2(e20, e21);
        }
        __syncthreads();

        // mv1: thread t owns cols t, 256+t, 512+t; weights arrive pre-duplicated (LDG.64)
        {
          const unsigned long long* w0p = (const unsigned long long*)&g_W2iou[t];
          const unsigned long long* w1p = (const unsigned long long*)&g_W2iou[DIM + t];
          const unsigned long long* w2p = (const unsigned long long*)&g_W2iou[2*DIM + t];
          #pragma unroll 4
          for (int k = 0; k < DIM; ++k) {
            const unsigned long long W0 = __ldg(w0p + (size_t)k * DIM3);
            const unsigned long long W1 = __ldg(w1p + (size_t)k * DIM3);
            const unsigned long long W2 = __ldg(w2p + (size_t)k * DIM3);
            const ulonglong2* hr = reinterpret_cast<const ulonglong2*>(&sm.fat.hT[k][0]);
            const ulonglong2 hA = hr[0], hB = hr[1], hC = hr[2], hD = hr[3];
            FMA2(A0[0], hA.x, W0); FMA2(A1[0], hA.x, W1); FMA2(A2[0], hA.x, W2);
            FMA2(A0[1], hA.y, W0); FMA2(A1[1], hA.y, W1); FMA2(A2[1], hA.y, W2);
            FMA2(A0[2], hB.x, W0); FMA2(A1[2], hB.x, W1); FMA2(A2[2], hB.x, W2);
            FMA2(A0[3], hB.y, W0); FMA2(A1[3], hB.y, W1); FMA2(A2[3], hB.y, W2);
            FMA2(A0[4], hC.x, W0); FMA2(A1[4], hC.x, W1); FMA2(A2[4], hC.x, W2);
            FMA2(A0[5], hC.y, W0); FMA2(A1[5], hC.y, W1); FMA2(A2[5], hC.y, W2);
            FMA2(A0[6], hD.x, W0); FMA2(A1[6], hD.x, W1); FMA2(A2[6], hD.x, W2);
            FMA2(A0[7], hD.y, W0); FMA2(A1[7], hD.y, W1); FMA2(A2[7], hD.y, W2);
          }
        }

        // gates: cc -> fcsh (same-thread overwrite), hh in regs
        float hh[TB];
        #pragma unroll
        for (int p = 0; p < 8; ++p) {
          float a0l, a0h, a1l, a1h, a2l, a2h;
          unpack2(A0[p], a0l, a0h);
          unpack2(A1[p], a1l, a1h);
          unpack2(A2[p], a2l, a2h);
          {
            const int b = 2*p;
            const float c = sigm(a0l) * tanhf(a2l) + sm.fat.fcsh[b][t];
            hh[b] = sigm(a1l) * tanhf(c);
            sm.fat.fcsh[b][t] = c;
          }
          {
            const int b = 2*p + 1;
            const float c = sigm(a0h) * tanhf(a2h) + sm.fat.fcsh[b][t];
            hh[b] = sigm(a1h) * tanhf(c);
            sm.fat.fcsh[b][t] = c;
          }
        }
        __syncthreads();
        #pragma unroll
        for (int b = 0; b < TB; ++b) sm.fat.hT[t][b] = hh[b];
        __syncthreads();

        // mv2: fpre = h @ Wfh + folded(embp_fx[parent_tok]); dup-packed weights
        unsigned long long F[8];
        #pragma unroll
        for (int p = 0; p < 8; ++p) {
          const float f0 = (snode[2*p]   >= 0) ? g_embp_fx[sptok[2*p]   * DIM + t] : 0.f;
          const float f1 = (snode[2*p+1] >= 0) ? g_embp_fx[sptok[2*p+1] * DIM + t] : 0.f;
          F[p] = pack2(f0, f1);
        }
        {
          const unsigned long long* wfp = (const unsigned long long*)&g_W2fh[t];
          #pragma unroll 4
          for (int k = 0; k < DIM; ++k) {
            const unsigned long long Wf = __ldg(wfp + (size_t)k * DIM);
            const ulonglong2* hr = reinterpret_cast<const ulonglong2*>(&sm.fat.hT[k][0]);
            const ulonglong2 hA = hr[0], hB = hr[1], hC = hr[2], hD = hr[3];
            FMA2(F[0], hA.x, Wf); FMA2(F[1], hA.y, Wf);
            FMA2(F[2], hB.x, Wf); FMA2(F[3], hB.y, Wf);
            FMA2(F[4], hC.x, Wf); FMA2(F[5], hC.y, Wf);
            FMA2(F[6], hD.x, Wf); FMA2(F[7], hD.y, Wf);
          }
        }

        // epilogue: hh from hT, cc from fcsh
        #pragma unroll
        for (int p = 0; p < 8; ++p) {
          float fl, fh2;
          unpack2(F[p], fl, fh2);
          #pragma unroll
          for (int q = 0; q < 2; ++q) {
            const int b = 2*p + q;
            const int gg = snode[b];
            if (gg < 0) continue;
            const float fv = q ? fh2 : fl;
            const float hval = sm.fat.hT[t][b];
            const float cval = sm.fat.fcsh[b][t];
            if ((gg & (NN - 1)) == 0) {
              g_croot[(gg >> 16) * DIM + t] = cval;
            } else {
              atomicAdd(&g_hsum [spar[b] * DIM + t], hval);
              atomicAdd(&g_fcsum[spar[b] * DIM + t], sigm(fv) * cval);
            }
          }
        }
      }
    }
    gbar();   // level complete on the whole grid
  }
}

// ---------------- phase 5: similarity head ----------------
__global__ void k_head(const float* __restrict__ Wh, const float* __restrict__ bh,
                       const float* __restrict__ Wp, const float* __restrict__ bp,
                       float* __restrict__ out) {
  __shared__ float vec[2 * DIM];
  __shared__ float s0[DIM], s1[DIM];
  const int t = threadIdx.x;
  const float cl = g_croot[t], cr = g_croot[DIM + t];
  vec[t] = cl * cr;
  vec[DIM + t] = fabsf(cl - cr);
  __syncthreads();
  float acc = bh[t];
  #pragma unroll 4
  for (int k = 0; k < 2 * DIM; ++k) acc = fmaf(vec[k], Wh[k * DIM + t], acc);
  const float hid = sigm(acc);
  s0[t] = hid * Wp[t * 2 + 0];
  s1[t] = hid * Wp[t * 2 + 1];
  __syncthreads();
  for (int s = DIM / 2; s > 0; s >>= 1) {
    if (t < s) { s0[t] += s0[t + s]; s1[t] += s1[t + s]; }
    __syncthreads();
  }
  if (t == 0) {
    const float l0 = s0[0] + bp[0], l1 = s1[0] + bp[1];
    const float m = fmaxf(l0, l1);
    const float e0 = expf(l0 - m), e1 = expf(l1 - m);
    const float inv = 1.0f / (e0 + e1);
    out[0] = e0 * inv;
    out[1] = e1 * inv;
  }
}

// ---------------- launcher (graph-capturable) ----------------
extern "C" void kernel_launch(void* const* d_in, const int* in_sizes, int n_in,
                              void* d_out, int out_size) {
  (void)in_sizes; (void)n_in;
  const int*   l_tok = (const int*)  d_in[0];
  const int*   l_par = (const int*)  d_in[1];
  const int*   r_tok = (const int*)  d_in[2];
  const int*   r_par = (const int*)  d_in[3];
  const float* emb   = (const float*)d_in[4];
  const float* Wioux = (const float*)d_in[5];
  const float* bioux = (const float*)d_in[6];
  const float* Wiouh = (const float*)d_in[7];
  const float* biouh = (const float*)d_in[8];
  const float* Wfx   = (const float*)d_in[9];
  const float* bfx   = (const float*)d_in[10];
  const float* Wfh   = (const float*)d_in[11];
  const float* bfh   = (const float*)d_in[12];
  const float* Wh    = (const float*)d_in[13];
  const float* bh    = (const float*)d_in[14];
  const float* Wp    = (const float*)d_in[15];
  const float* bp    = (const float*)d_in[16];
  float* out = (float*)d_out;
  (void)out_size;

  void *p_hs, *p_fc, *p_cnt, *p_cur, *p_mk;
  cudaGetSymbolAddress(&p_hs,  g_hsum);
  cudaGetSymbolAddress(&p_fc,  g_fcsum);
  cudaGetSymbolAddress(&p_cnt, g_cnt);
  cudaGetSymbolAddress(&p_cur, g_cur);
  cudaGetSymbolAddress(&p_mk,  g_mark);
  cudaMemsetAsync(p_hs,  0, sizeof(float) * 2ull * NN * DIM);
  cudaMemsetAsync(p_fc,  0, sizeof(float) * 2ull * NN * DIM);
  cudaMemsetAsync(p_cnt, 0, sizeof(int) * 2 * MAXLV);
  cudaMemsetAsync(p_cur, 0, sizeof(int) * 2 * MAXLV);
  cudaMemsetAsync(p_mk,  0, sizeof(int) * 2 * NN);

  k_prep<<<EMBB + DEPB, 256>>>(emb, Wioux, bioux, biouh, Wfx, bfx, bfh, Wfh,
                               l_par, r_par, l_tok, r_tok);
  k_pack<<<(DIM * DIM3 + 255) / 256, 256>>>(Wiouh, Wfh);
  k_scan<<<1, 256>>>();
  k_scatlf<<<DEPB + (2 * NN + 3) / 4, 256>>>();

  int dev = 0;
  cudaGetDevice(&dev);
  int sms = 148;
  cudaDeviceGetAttribute(&sms, cudaDevAttrMultiProcessorCount, dev);
  int maxb = 1;
  cudaOccupancyMaxActiveBlocksPerMultiprocessor(&maxb, k_levels, 256, 0);
  if (maxb > 2) maxb = 2;
  if (maxb < 1) maxb = 1;
  k_levels<<<sms * maxb, 256>>>(Wiouh, Wfh);   // grid == guaranteed-resident blocks (gbar-safe)

  k_head<<<1, DIM>>>(Wh, bh, Wp, bp, out);
}

// round 14
// speedup vs baseline: 2.1446x; 1.1314x over previous
#include <cuda_runtime.h>

#define NN     65536
#define VOCAB  1000
#define DIM    256
#define DIM3   768
#define MAXLV  192
#define TB     16                 // fat-path nodes per chunk
#define PAD    20
#define WTHR   768                // wide-path level-size threshold (was 64)
#define EMBB   (VOCAB / 4)        // 250 embproj blocks
#define DEPB   (2 * NN / 256)     // 512 depth blocks

// ---------------- scratch (static device allocations only) ----------------
static __device__ float g_hsum [2 * NN * DIM];    // child h sums   (134 MB)
static __device__ float g_fcsum[2 * NN * DIM];    // child f*c sums (134 MB)
static __device__ float g_embp_iou[VOCAB * DIM3]; // emb@Wioux + bioux + biouh
static __device__ float g_embp_fx [VOCAB * DIM];  // emb@Wfx   + bfx   + bfh
static __device__ float g_leaf_c  [VOCAB * DIM];
static __device__ float g_leaf_h  [VOCAB * DIM];
static __device__ float g_fpreL   [VOCAB * DIM];  // leaf_h @ Wfh per token
static __device__ int   g_sched[2 * NN];
static __device__ int   g_par  [2 * NN];
static __device__ int   g_tok  [2 * NN];
static __device__ int   g_depth[2 * NN];
static __device__ int   g_mark [2 * NN];          // 1 = internal node
static __device__ int   g_cnt  [2 * MAXLV];
static __device__ int   g_cur  [2 * MAXLV];
static __device__ int   g_start[2 * MAXLV];
static __device__ int   g_lo[MAXLV];
static __device__ int   g_hi[MAXLV];
static __device__ float g_croot[2 * DIM];
static __device__ unsigned g_barcnt;
static __device__ unsigned g_bargen;

__device__ __forceinline__ float sigm(float x) { return 1.0f / (1.0f + expf(-x)); }

// ---- f32x2 helpers (sm_100+; ptxas never auto-fuses FFMA2 from C++) ----
__device__ __forceinline__ unsigned long long pack2(float lo, float hi) {
  unsigned long long r;
  asm("mov.b64 %0, {%1, %2};" : "=l"(r) : "f"(lo), "f"(hi));
  return r;
}
__device__ __forceinline__ void unpack2(unsigned long long v, float& lo, float& hi) {
  asm("mov.b64 {%0, %1}, %2;" : "=f"(lo), "=f"(hi) : "l"(v));
}
#define FMA2(d, h, w) asm("fma.rn.f32x2 %0, %1, %2, %0;" : "+l"(d) : "l"(h), "l"(w))

// ---------------- phase 1 (FUSED): embedding projections  ∥  depth+hist ----------------
__global__ void k_prep(const float* __restrict__ emb,
                       const float* __restrict__ Wioux, const float* __restrict__ bioux,
                       const float* __restrict__ biouh,
                       const float* __restrict__ Wfx,   const float* __restrict__ bfx,
                       const float* __restrict__ bfh,
                       const float* __restrict__ Wfh,
                       const int* __restrict__ lpar, const int* __restrict__ rpar,
                       const int* __restrict__ ltok, const int* __restrict__ rtok) {
  const int t = threadIdx.x;
  if (blockIdx.x < EMBB) {
    __shared__ float xs[4][DIM];
    const int v0 = blockIdx.x * 4;
    #pragma unroll
    for (int j = 0; j < 4; ++j) xs[j][t] = emb[(v0 + j) * DIM + t];
    __syncthreads();

    const float b0 = bioux[t]           + biouh[t];
    const float b1 = bioux[DIM + t]     + biouh[DIM + t];
    const float b2 = bioux[2*DIM + t]   + biouh[2*DIM + t];
    const float bf = bfx[t] + bfh[t];
    float a0[4], a1[4], a2[4], af[4];
    #pragma unroll
    for (int j = 0; j < 4; ++j) { a0[j] = b0; a1[j] = b1; a2[j] = b2; af[j] = bf; }

    #pragma unroll 4
    for (int k = 0; k < DIM; ++k) {
      const float w0 = Wioux[k*DIM3 + t];
      const float w1 = Wioux[k*DIM3 + DIM + t];
      const float w2 = Wioux[k*DIM3 + 2*DIM + t];
      const float wf = Wfx  [k*DIM + t];
      #pragma unroll
      for (int j = 0; j < 4; ++j) {
        const float xv = xs[j][k];
        a0[j] = fmaf(xv, w0, a0[j]);
        a1[j] = fmaf(xv, w1, a1[j]);
        a2[j] = fmaf(xv, w2, a2[j]);
        af[j] = fmaf(xv, wf, af[j]);
      }
    }

    float hj[4];
    #pragma unroll
    for (int j = 0; j < 4; ++j) {
      const int v = v0 + j;
      g_embp_iou[v*DIM3 + t]         = a0[j];
      g_embp_iou[v*DIM3 + DIM + t]   = a1[j];
      g_embp_iou[v*DIM3 + 2*DIM + t] = a2[j];
      g_embp_fx [v*DIM + t]          = af[j];
      const float c = sigm(a0[j]) * tanhf(a2[j]);
      const float h = sigm(a1[j]) * tanhf(c);
      g_leaf_c[v*DIM + t] = c;
      g_leaf_h[v*DIM + t] = h;
      hj[j] = h;
    }
    __syncthreads();
    #pragma unroll
    for (int j = 0; j < 4; ++j) xs[j][t] = hj[j];
    __syncthreads();

    float fp[4] = {0.f, 0.f, 0.f, 0.f};
    #pragma unroll 4
    for (int k = 0; k < DIM; ++k) {
      const float wf = Wfh[k*DIM + t];
      #pragma unroll
      for (int j = 0; j < 4; ++j) fp[j] = fmaf(xs[j][k], wf, fp[j]);
    }
    #pragma unroll
    for (int j = 0; j < 4; ++j) g_fpreL[(v0 + j)*DIM + t] = fp[j];
  } else {
    const int g = (blockIdx.x - EMBB) * 256 + t;
    const int tree = g >> 16, node = g & (NN - 1);
    const int* par = tree ? rpar : lpar;
    const int* tok = tree ? rtok : ltok;
    int d = 0, i = node;
    while (i != 0) { i = par[i]; ++d; }
    if (d > MAXLV - 1) d = MAXLV - 1;
    g_depth[g] = d;
    g_par[g] = (tree << 16) | par[node];
    g_tok[g] = tok[node];
    if (node != 0) {
      const int pg = (tree << 16) | par[node];
      if (atomicExch(&g_mark[pg], 1) == 0)
        atomicAdd(&g_cnt[tree * MAXLV + (d - 1)], 1);
    }
  }
}

// ---------------- phase 2: level offsets (smem-staged serial scan) ----------------
__global__ void k_scan() {
  __shared__ int c0[MAXLV], c1[MAXLV];
  const int t = threadIdx.x;
  if (t < MAXLV) { c0[t] = g_cnt[t]; c1[t] = g_cnt[MAXLV + t]; }
  __syncthreads();
  if (t == 0) {
    int off = 0;
    for (int L = MAXLV - 1; L >= 0; --L) {
      g_lo[L] = off;
      g_start[0 * MAXLV + L] = off; off += c0[L];
      g_start[1 * MAXLV + L] = off; off += c1[L];
      g_hi[L] = off;
    }
  }
}

// ---------------- phase 3 (FUSED): bucket internal nodes  ∥  bulk leaf pass ----------------
__global__ void k_scatlf() {
  const int t = threadIdx.x;
  if (blockIdx.x < DEPB) {
    const int g = blockIdx.x * 256 + t;
    if (g_mark[g] == 0) return;
    const int tree = g >> 16;
    const int d = g_depth[g];
    const int pos = g_start[tree * MAXLV + d] + atomicAdd(&g_cur[tree * MAXLV + d], 1);
    g_sched[pos] = g;
  } else {
    const int node = (blockIdx.x - DEPB) * 4 + (t >> 6);
    if (node >= 2 * NN) return;
    if (g_mark[node] != 0) return;
    const int t4 = (t & 63) * 4;
    const int pg = g_par[node];
    const int v  = g_tok[node];
    const int pv = g_tok[pg];
    const float4 h4 = *(const float4*)&g_leaf_h [v  * DIM + t4];
    const float4 c4 = *(const float4*)&g_leaf_c [v  * DIM + t4];
    const float4 fp = *(const float4*)&g_fpreL  [v  * DIM + t4];
    const float4 fx = *(const float4*)&g_embp_fx[pv * DIM + t4];
    float* hs = &g_hsum [pg * DIM + t4];
    float* fc = &g_fcsum[pg * DIM + t4];
    atomicAdd(hs + 0, h4.x); atomicAdd(hs + 1, h4.y);
    atomicAdd(hs + 2, h4.z); atomicAdd(hs + 3, h4.w);
    atomicAdd(fc + 0, sigm(fp.x + fx.x) * c4.x);
    atomicAdd(fc + 1, sigm(fp.y + fx.y) * c4.y);
    atomicAdd(fc + 2, sigm(fp.z + fx.z) * c4.z);
    atomicAdd(fc + 3, sigm(fp.w + fx.w) * c4.w);
  }
}

// ---------------- software grid barrier ----------------
__device__ __forceinline__ void gbar() {
  __threadfence();
  __syncthreads();
  if (threadIdx.x == 0) {
    volatile unsigned* vg = &g_bargen;
    const unsigned my = *vg;
    const unsigned tkt = atomicAdd(&g_barcnt, 1u);
    if (tkt == gridDim.x - 1) {
      g_barcnt = 0;
      __threadfence();
      atomicAdd(&g_bargen, 1u);
    } else {
      while (*vg == my) { __nanosleep(64); }
    }
    __threadfence();
  }
  __syncthreads();
}

// ---------------- phase 4: persistent wavefront ----------------
// Fat path (cnt > WTHR): 16-node chunks, f32x2 node-pair accumulators (R9 config).
// Wide path (cnt <= WTHR): 1 node/block, k split across 8 warps — full block
//   utilization on mid/small levels where chunk-wave quantization dominates.
__global__ void __launch_bounds__(256, 2) k_levels(const float* __restrict__ Wiouh,
                                                   const float* __restrict__ Wfh) {
  __shared__ __align__(16) union {
    struct { float hT[DIM][PAD]; float fcsh[TB][DIM]; } fat;                      // 36 KB
    struct { float hs[DIM]; float fc[DIM]; float hv[DIM]; float red[8][DIM3]; } wide; // 27 KB
  } sm;
  __shared__ int snode[TB], spar[TB], stok[TB], sptok[TB];
  const int t = threadIdx.x;
  const int w = t >> 5, l = t & 31;

  for (int L = MAXLV - 1; L >= 0; --L) {
    const int lo = g_lo[L], hi = g_hi[L];
    const int cnt = hi - lo;
    if (cnt == 0) continue;                  // identical on all blocks

    if (cnt <= WTHR) {
      // ---------- wide path: node-per-block, k split by warp ----------
      for (int idx = lo + (int)blockIdx.x; idx < hi; idx += gridDim.x) {
        const int gg = g_sched[idx];
        const int pg = g_par[gg];
        const int tok = g_tok[gg], ptok = g_tok[pg];
        sm.wide.hs[t] = __ldcg(&g_hsum [gg * DIM + t]);
        sm.wide.fc[t] = __ldcg(&g_fcsum[gg * DIM + t]);
        __syncthreads();

        {
          const int k0 = w << 5;
          #pragma unroll 2
          for (int j = 0; j < 24; ++j) {
            float p = 0.f;
            const float* col = Wiouh + k0 * DIM3 + l + 32*j;
            #pragma unroll
            for (int kk = 0; kk < 32; ++kk)
              p = fmaf(sm.wide.hs[k0 + kk], __ldg(col + kk * DIM3), p);
            sm.wide.red[w][l + 32*j] = p;
          }
        }
        __syncthreads();

        float i0 = 0.f, o0 = 0.f, u0 = 0.f;
        #pragma unroll
        for (int w2 = 0; w2 < 8; ++w2) {
          i0 += sm.wide.red[w2][t];
          o0 += sm.wide.red[w2][DIM + t];
          u0 += sm.wide.red[w2][2*DIM + t];
        }
        const int tv = tok * DIM3;
        i0 += g_embp_iou[tv + t];
        o0 += g_embp_iou[tv + DIM + t];
        u0 += g_embp_iou[tv + 2*DIM + t];
        const float cval = sigm(i0) * tanhf(u0) + sm.wide.fc[t];
        const float hval = sigm(o0) * tanhf(cval);
        __syncthreads();
        sm.wide.hv[t] = hval;
        __syncthreads();

        {
          const int k0 = w << 5;
          #pragma unroll 2
          for (int j = 0; j < 8; ++j) {
            float p = 0.f;
            const float* col = Wfh + k0 * DIM + l + 32*j;
            #pragma unroll
            for (int kk = 0; kk < 32; ++kk)
              p = fmaf(sm.wide.hv[k0 + kk], __ldg(col + kk * DIM), p);
            sm.wide.red[w][l + 32*j] = p;
          }
        }
        __syncthreads();

        float f = g_embp_fx[ptok * DIM + t];
        #pragma unroll
        for (int w2 = 0; w2 < 8; ++w2) f += sm.wide.red[w2][t];

        if ((gg & (NN - 1)) == 0) {
          g_croot[(gg >> 16) * DIM + t] = cval;
        } else {
          atomicAdd(&g_hsum [pg * DIM + t], hval);
          atomicAdd(&g_fcsum[pg * DIM + t], sigm(f) * cval);
        }
        __syncthreads();
      }
    } else {
      // ---------- fat path: 16-node chunks, f32x2 (R9-measured config) ----------
      const int nch = (cnt + TB - 1) / TB;
      for (int ch = blockIdx.x; ch < nch; ch += gridDim.x) {
        const int base = lo + ch * TB;
        __syncthreads();                 // previous chunk done with shared

        if (t < TB) {
          const int gg = (base + t < hi) ? g_sched[base + t] : -1;
          snode[t] = gg;
          if (gg >= 0) {
            const int pg = g_par[gg];
            spar[t] = pg; stok[t] = g_tok[gg]; sptok[t] = g_tok[pg];
          }
        }
        __syncthreads();

        #pragma unroll
        for (int b = 0; b < TB; ++b) {
          const int gg = snode[b];
          sm.fat.hT[t][b]   = (gg >= 0) ? __ldcg(&g_hsum [gg * DIM + t]) : 0.0f;
          sm.fat.fcsh[b][t] = (gg >= 0) ? __ldcg(&g_fcsum[gg * DIM + t]) : 0.0f;
        }

        unsigned long long A0[8], A1[8], A2[8];
        #pragma unroll
        for (int p = 0; p < 8; ++p) {
          float e00 = 0.f, e01 = 0.f, e10 = 0.f, e11 = 0.f, e20 = 0.f, e21 = 0.f;
          if (snode[2*p] >= 0) {
            const int tv = stok[2*p] * DIM3;
            e00 = g_embp_iou[tv + t]; e10 = g_embp_iou[tv + DIM + t]; e20 = g_embp_iou[tv + 2*DIM + t];
          }
          if (snode[2*p+1] >= 0) {
            const int tv = stok[2*p+1] * DIM3;
            e01 = g_embp_iou[tv + t]; e11 = g_embp_iou[tv + DIM + t]; e21 = g_embp_iou[tv + 2*DIM + t];
          }
          A0[p] = pack2(e00, e01); A1[p] = pack2(e10, e11); A2[p] = pack2(e20, e21);
        }
        __syncthreads();

        // mv1: thread t owns cols t, 256+t, 512+t; FFMA2 over node pairs
        #pragma unroll 4
        for (int k = 0; k < DIM; ++k) {
          const float* wr = Wiouh + k * DIM3 + t;
          const float w0 = __ldg(wr), w1 = __ldg(wr + DIM), w2 = __ldg(wr + 2*DIM);
          const unsigned long long W0 = pack2(w0, w0), W1 = pack2(w1, w1), W2 = pack2(w2, w2);
          const ulonglong2* hr = reinterpret_cast<const ulonglong2*>(&sm.fat.hT[k][0]);
          const ulonglong2 hA = hr[0], hB = hr[1], hC = hr[2], hD = hr[3];
          FMA2(A0[0], hA.x, W0); FMA2(A1[0], hA.x, W1); FMA2(A2[0], hA.x, W2);
          FMA2(A0[1], hA.y, W0); FMA2(A1[1], hA.y, W1); FMA2(A2[1], hA.y, W2);
          FMA2(A0[2], hB.x, W0); FMA2(A1[2], hB.x, W1); FMA2(A2[2], hB.x, W2);
          FMA2(A0[3], hB.y, W0); FMA2(A1[3], hB.y, W1); FMA2(A2[3], hB.y, W2);
          FMA2(A0[4], hC.x, W0); FMA2(A1[4], hC.x, W1); FMA2(A2[4], hC.x, W2);
          FMA2(A0[5], hC.y, W0); FMA2(A1[5], hC.y, W1); FMA2(A2[5], hC.y, W2);
          FMA2(A0[6], hD.x, W0); FMA2(A1[6], hD.x, W1); FMA2(A2[6], hD.x, W2);
          FMA2(A0[7], hD.y, W0); FMA2(A1[7], hD.y, W1); FMA2(A2[7], hD.y, W2);
        }

        // gates: cc -> fcsh (same-thread overwrite), hh in regs
        float hh[TB];
        #pragma unroll
        for (int p = 0; p < 8; ++p) {
          float a0l, a0h, a1l, a1h, a2l, a2h;
          unpack2(A0[p], a0l, a0h);
          unpack2(A1[p], a1l, a1h);
          unpack2(A2[p], a2l, a2h);
          {
            const int b = 2*p;
            const float c = sigm(a0l) * tanhf(a2l) + sm.fat.fcsh[b][t];
            hh[b] = sigm(a1l) * tanhf(c);
            sm.fat.fcsh[b][t] = c;
          }
          {
            const int b = 2*p + 1;
            const float c = sigm(a0h) * tanhf(a2h) + sm.fat.fcsh[b][t];
            hh[b] = sigm(a1h) * tanhf(c);
            sm.fat.fcsh[b][t] = c;
          }
        }
        __syncthreads();
        #pragma unroll
        for (int b = 0; b < TB; ++b) sm.fat.hT[t][b] = hh[b];
        __syncthreads();

        // mv2: fpre = h @ Wfh + folded(embp_fx[parent_tok])
        unsigned long long F[8];
        #pragma unroll
        for (int p = 0; p < 8; ++p) {
          const float f0 = (snode[2*p]   >= 0) ? g_embp_fx[sptok[2*p]   * DIM + t] : 0.f;
          const float f1 = (snode[2*p+1] >= 0) ? g_embp_fx[sptok[2*p+1] * DIM + t] : 0.f;
          F[p] = pack2(f0, f1);
        }
        #pragma unroll 4
        for (int k = 0; k < DIM; ++k) {
          const float wf = __ldg(Wfh + k * DIM + t);
          const unsigned long long Wf = pack2(wf, wf);
          const ulonglong2* hr = reinterpret_cast<const ulonglong2*>(&sm.fat.hT[k][0]);
          const ulonglong2 hA = hr[0], hB = hr[1], hC = hr[2], hD = hr[3];
          FMA2(F[0], hA.x, Wf); FMA2(F[1], hA.y, Wf);
          FMA2(F[2], hB.x, Wf); FMA2(F[3], hB.y, Wf);
          FMA2(F[4], hC.x, Wf); FMA2(F[5], hC.y, Wf);
          FMA2(F[6], hD.x, Wf); FMA2(F[7], hD.y, Wf);
        }

        // epilogue: hh from hT, cc from fcsh
        #pragma unroll
        for (int p = 0; p < 8; ++p) {
          float fl, fh2;
          unpack2(F[p], fl, fh2);
          #pragma unroll
          for (int q = 0; q < 2; ++q) {
            const int b = 2*p + q;
            const int gg = snode[b];
            if (gg < 0) continue;
            const float fv = q ? fh2 : fl;
            const float hval = sm.fat.hT[t][b];
            const float cval = sm.fat.fcsh[b][t];
            if ((gg & (NN - 1)) == 0) {
              g_croot[(gg >> 16) * DIM + t] = cval;
            } else {
              atomicAdd(&g_hsum [spar[b] * DIM + t], hval);
              atomicAdd(&g_fcsum[spar[b] * DIM + t], sigm(fv) * cval);
            }
          }
        }
      }
    }
    gbar();   // level complete on the whole grid
  }
}

// ---------------- phase 5: similarity head ----------------
__global__ void k_head(const float* __restrict__ Wh, const float* __restrict__ bh,
                       const float* __restrict__ Wp, const float* __restrict__ bp,
                       float* __restrict__ out) {
  __shared__ float vec[2 * DIM];
  __shared__ float s0[DIM], s1[DIM];
  const int t = threadIdx.x;
  const float cl = g_croot[t], cr = g_croot[DIM + t];
  vec[t] = cl * cr;
  vec[DIM + t] = fabsf(cl - cr);
  __syncthreads();
  float acc = bh[t];
  #pragma unroll 4
  for (int k = 0; k < 2 * DIM; ++k) acc = fmaf(vec[k], Wh[k * DIM + t], acc);
  const float hid = sigm(acc);
  s0[t] = hid * Wp[t * 2 + 0];
  s1[t] = hid * Wp[t * 2 + 1];
  __syncthreads();
  for (int s = DIM / 2; s > 0; s >>= 1) {
    if (t < s) { s0[t] += s0[t + s]; s1[t] += s1[t + s]; }
    __syncthreads();
  }
  if (t == 0) {
    const float l0 = s0[0] + bp[0], l1 = s1[0] + bp[1];
    const float m = fmaxf(l0, l1);
    const float e0 = expf(l0 - m), e1 = expf(l1 - m);
    const float inv = 1.0f / (e0 + e1);
    out[0] = e0 * inv;
    out[1] = e1 * inv;
  }
}

// ---------------- launcher (graph-capturable) ----------------
extern "C" void kernel_launch(void* const* d_in, const int* in_sizes, int n_in,
                              void* d_out, int out_size) {
  (void)in_sizes; (void)n_in;
  const int*   l_tok = (const int*)  d_in[0];
  const int*   l_par = (const int*)  d_in[1];
  const int*   r_tok = (const int*)  d_in[2];
  const int*   r_par = (const int*)  d_in[3];
  const float* emb   = (const float*)d_in[4];
  const float* Wioux = (const float*)d_in[5];
  const float* bioux = (const float*)d_in[6];
  const float* Wiouh = (const float*)d_in[7];
  const float* biouh = (const float*)d_in[8];
  const float* Wfx   = (const float*)d_in[9];
  const float* bfx   = (const float*)d_in[10];
  const float* Wfh   = (const float*)d_in[11];
  const float* bfh   = (const float*)d_in[12];
  const float* Wh    = (const float*)d_in[13];
  const float* bh    = (const float*)d_in[14];
  const float* Wp    = (const float*)d_in[15];
  const float* bp    = (const float*)d_in[16];
  float* out = (float*)d_out;
  (void)out_size;

  void *p_hs, *p_fc, *p_cnt, *p_cur, *p_mk;
  cudaGetSymbolAddress(&p_hs,  g_hsum);
  cudaGetSymbolAddress(&p_fc,  g_fcsum);
  cudaGetSymbolAddress(&p_cnt, g_cnt);
  cudaGetSymbolAddress(&p_cur, g_cur);
  cudaGetSymbolAddress(&p_mk,  g_mark);
  cudaMemsetAsync(p_hs,  0, sizeof(float) * 2ull * NN * DIM);
  cudaMemsetAsync(p_fc,  0, sizeof(float) * 2ull * NN * DIM);
  cudaMemsetAsync(p_cnt, 0, sizeof(int) * 2 * MAXLV);
  cudaMemsetAsync(p_cur, 0, sizeof(int) * 2 * MAXLV);
  cudaMemsetAsync(p_mk,  0, sizeof(int) * 2 * NN);

  k_prep<<<EMBB + DEPB, 256>>>(emb, Wioux, bioux, biouh, Wfx, bfx, bfh, Wfh,
                               l_par, r_par, l_tok, r_tok);
  k_scan<<<1, 256>>>();
  k_scatlf<<<DEPB + (2 * NN + 3) / 4, 256>>>();

  int dev = 0;
  cudaGetDevice(&dev);
  int sms = 148;
  cudaDeviceGetAttribute(&sms, cudaDevAttrMultiProcessorCount, dev);
  int maxb = 1;
  cudaOccupancyMaxActiveBlocksPerMultiprocessor(&maxb, k_levels, 256, 0);
  if (maxb > 2) maxb = 2;
  if (maxb < 1) maxb = 1;
  k_levels<<<sms * maxb, 256>>>(Wiouh, Wfh);   // grid == guaranteed-resident blocks (gbar-safe)

  k_head<<<1, DIM>>>(Wh, bh, Wp, bp, out);
}

// round 15
// speedup vs baseline: 2.2054x; 1.0284x over previous
#include <cuda_runtime.h>

#define NN     65536
#define VOCAB  1000
#define DIM    256
#define DIM3   768
#define MAXLV  192
#define TB     16                 // fat-path nodes per chunk
#define PAD    20
#define WTHR   1152               // wide-path level-size threshold (crossover-tuned)
#define EMBB   (VOCAB / 4)        // 250 embproj blocks
#define DEPB   (2 * NN / 256)     // 512 depth blocks

// ---------------- scratch (static device allocations only) ----------------
static __device__ float g_hsum [2 * NN * DIM];    // child h sums   (134 MB)
static __device__ float g_fcsum[2 * NN * DIM];    // child f*c sums (134 MB)
static __device__ float g_embp_iou[VOCAB * DIM3]; // emb@Wioux + bioux + biouh
static __device__ float g_embp_fx [VOCAB * DIM];  // emb@Wfx   + bfx   + bfh
static __device__ float g_leaf_c  [VOCAB * DIM];
static __device__ float g_leaf_h  [VOCAB * DIM];
static __device__ float g_fpreL   [VOCAB * DIM];  // leaf_h @ Wfh per token
static __device__ int   g_sched[2 * NN];
static __device__ int   g_par  [2 * NN];
static __device__ int   g_tok  [2 * NN];
static __device__ int   g_depth[2 * NN];
static __device__ int   g_mark [2 * NN];          // 1 = internal node
static __device__ int   g_cnt  [2 * MAXLV];
static __device__ int   g_cur  [2 * MAXLV];
static __device__ int   g_start[2 * MAXLV];
static __device__ int   g_lo[MAXLV];
static __device__ int   g_hi[MAXLV];
static __device__ float g_croot[2 * DIM];
static __device__ float g_hpart[8][DIM];          // head matvec partials
static __device__ unsigned g_barcnt;
static __device__ unsigned g_bargen;

__device__ __forceinline__ float sigm(float x) { return 1.0f / (1.0f + expf(-x)); }

// ---- f32x2 helpers (sm_100+; ptxas never auto-fuses FFMA2 from C++) ----
__device__ __forceinline__ unsigned long long pack2(float lo, float hi) {
  unsigned long long r;
  asm("mov.b64 %0, {%1, %2};" : "=l"(r) : "f"(lo), "f"(hi));
  return r;
}
__device__ __forceinline__ void unpack2(unsigned long long v, float& lo, float& hi) {
  asm("mov.b64 {%0, %1}, %2;" : "=f"(lo), "=f"(hi) : "l"(v));
}
#define FMA2(d, h, w) asm("fma.rn.f32x2 %0, %1, %2, %0;" : "+l"(d) : "l"(h), "l"(w))

// ---------------- phase 1 (FUSED): embedding projections  ∥  depth+hist ----------------
__global__ void k_prep(const float* __restrict__ emb,
                       const float* __restrict__ Wioux, const float* __restrict__ bioux,
                       const float* __restrict__ biouh,
                       const float* __restrict__ Wfx,   const float* __restrict__ bfx,
                       const float* __restrict__ bfh,
                       const float* __restrict__ Wfh,
                       const int* __restrict__ lpar, const int* __restrict__ rpar,
                       const int* __restrict__ ltok, const int* __restrict__ rtok) {
  const int t = threadIdx.x;
  if (blockIdx.x < EMBB) {
    __shared__ float xs[4][DIM];
    const int v0 = blockIdx.x * 4;
    #pragma unroll
    for (int j = 0; j < 4; ++j) xs[j][t] = emb[(v0 + j) * DIM + t];
    __syncthreads();

    const float b0 = bioux[t]           + biouh[t];
    const float b1 = bioux[DIM + t]     + biouh[DIM + t];
    const float b2 = bioux[2*DIM + t]   + biouh[2*DIM + t];
    const float bf = bfx[t] + bfh[t];
    float a0[4], a1[4], a2[4], af[4];
    #pragma unroll
    for (int j = 0; j < 4; ++j) { a0[j] = b0; a1[j] = b1; a2[j] = b2; af[j] = bf; }

    #pragma unroll 4
    for (int k = 0; k < DIM; ++k) {
      const float w0 = Wioux[k*DIM3 + t];
      const float w1 = Wioux[k*DIM3 + DIM + t];
      const float w2 = Wioux[k*DIM3 + 2*DIM + t];
      const float wf = Wfx  [k*DIM + t];
      #pragma unroll
      for (int j = 0; j < 4; ++j) {
        const float xv = xs[j][k];
        a0[j] = fmaf(xv, w0, a0[j]);
        a1[j] = fmaf(xv, w1, a1[j]);
        a2[j] = fmaf(xv, w2, a2[j]);
        af[j] = fmaf(xv, wf, af[j]);
      }
    }

    float hj[4];
    #pragma unroll
    for (int j = 0; j < 4; ++j) {
      const int v = v0 + j;
      g_embp_iou[v*DIM3 + t]         = a0[j];
      g_embp_iou[v*DIM3 + DIM + t]   = a1[j];
      g_embp_iou[v*DIM3 + 2*DIM + t] = a2[j];
      g_embp_fx [v*DIM + t]          = af[j];
      const float c = sigm(a0[j]) * tanhf(a2[j]);
      const float h = sigm(a1[j]) * tanhf(c);
      g_leaf_c[v*DIM + t] = c;
      g_leaf_h[v*DIM + t] = h;
      hj[j] = h;
    }
    __syncthreads();
    #pragma unroll
    for (int j = 0; j < 4; ++j) xs[j][t] = hj[j];
    __syncthreads();

    float fp[4] = {0.f, 0.f, 0.f, 0.f};
    #pragma unroll 4
    for (int k = 0; k < DIM; ++k) {
      const float wf = Wfh[k*DIM + t];
      #pragma unroll
      for (int j = 0; j < 4; ++j) fp[j] = fmaf(xs[j][k], wf, fp[j]);
    }
    #pragma unroll
    for (int j = 0; j < 4; ++j) g_fpreL[(v0 + j)*DIM + t] = fp[j];
  } else {
    const int g = (blockIdx.x - EMBB) * 256 + t;
    const int tree = g >> 16, node = g & (NN - 1);
    const int* par = tree ? rpar : lpar;
    const int* tok = tree ? rtok : ltok;
    int d = 0, i = node;
    while (i != 0) { i = par[i]; ++d; }
    if (d > MAXLV - 1) d = MAXLV - 1;
    g_depth[g] = d;
    g_par[g] = (tree << 16) | par[node];
    g_tok[g] = tok[node];
    if (node != 0) {
      const int pg = (tree << 16) | par[node];
      if (atomicExch(&g_mark[pg], 1) == 0)
        atomicAdd(&g_cnt[tree * MAXLV + (d - 1)], 1);
    }
  }
}

// ---------------- phase 2: level offsets (smem-staged serial scan) ----------------
__global__ void k_scan() {
  __shared__ int c0[MAXLV], c1[MAXLV];
  const int t = threadIdx.x;
  if (t < MAXLV) { c0[t] = g_cnt[t]; c1[t] = g_cnt[MAXLV + t]; }
  __syncthreads();
  if (t == 0) {
    int off = 0;
    for (int L = MAXLV - 1; L >= 0; --L) {
      g_lo[L] = off;
      g_start[0 * MAXLV + L] = off; off += c0[L];
      g_start[1 * MAXLV + L] = off; off += c1[L];
      g_hi[L] = off;
    }
  }
}

// ---------------- phase 3 (FUSED): bucket internal nodes  ∥  bulk leaf pass ----------------
__global__ void k_scatlf() {
  const int t = threadIdx.x;
  if (blockIdx.x < DEPB) {
    const int g = blockIdx.x * 256 + t;
    if (g_mark[g] == 0) return;
    const int tree = g >> 16;
    const int d = g_depth[g];
    const int pos = g_start[tree * MAXLV + d] + atomicAdd(&g_cur[tree * MAXLV + d], 1);
    g_sched[pos] = g;
  } else {
    const int node = (blockIdx.x - DEPB) * 4 + (t >> 6);
    if (node >= 2 * NN) return;
    if (g_mark[node] != 0) return;
    const int t4 = (t & 63) * 4;
    const int pg = g_par[node];
    const int v  = g_tok[node];
    const int pv = g_tok[pg];
    const float4 h4 = *(const float4*)&g_leaf_h [v  * DIM + t4];
    const float4 c4 = *(const float4*)&g_leaf_c [v  * DIM + t4];
    const float4 fp = *(const float4*)&g_fpreL  [v  * DIM + t4];
    const float4 fx = *(const float4*)&g_embp_fx[pv * DIM + t4];
    float* hs = &g_hsum [pg * DIM + t4];
    float* fc = &g_fcsum[pg * DIM + t4];
    atomicAdd(hs + 0, h4.x); atomicAdd(hs + 1, h4.y);
    atomicAdd(hs + 2, h4.z); atomicAdd(hs + 3, h4.w);
    atomicAdd(fc + 0, sigm(fp.x + fx.x) * c4.x);
    atomicAdd(fc + 1, sigm(fp.y + fx.y) * c4.y);
    atomicAdd(fc + 2, sigm(fp.z + fx.z) * c4.z);
    atomicAdd(fc + 3, sigm(fp.w + fx.w) * c4.w);
  }
}

// ---------------- software grid barrier ----------------
__device__ __forceinline__ void gbar() {
  __threadfence();
  __syncthreads();
  if (threadIdx.x == 0) {
    volatile unsigned* vg = &g_bargen;
    const unsigned my = *vg;
    const unsigned tkt = atomicAdd(&g_barcnt, 1u);
    if (tkt == gridDim.x - 1) {
      g_barcnt = 0;
      __threadfence();
      atomicAdd(&g_bargen, 1u);
    } else {
      while (*vg == my) { __nanosleep(64); }
    }
    __threadfence();
  }
  __syncthreads();
}

// ---------------- phase 4: persistent wavefront ----------------
// Fat path (cnt > WTHR): 16-node chunks, f32x2 node-pair accumulators (R9 config).
// Wide path (cnt <= WTHR): 1 node/block, k split across 8 warps.
__global__ void __launch_bounds__(256, 2) k_levels(const float* __restrict__ Wiouh,
                                                   const float* __restrict__ Wfh) {
  __shared__ __align__(16) union {
    struct { float hT[DIM][PAD]; float fcsh[TB][DIM]; } fat;                      // 36 KB
    struct { float hs[DIM]; float fc[DIM]; float hv[DIM]; float red[8][DIM3]; } wide; // 27 KB
  } sm;
  __shared__ int snode[TB], spar[TB], stok[TB], sptok[TB];
  const int t = threadIdx.x;
  const int w = t >> 5, l = t & 31;

  for (int L = MAXLV - 1; L >= 0; --L) {
    const int lo = g_lo[L], hi = g_hi[L];
    const int cnt = hi - lo;
    if (cnt == 0) continue;                  // identical on all blocks

    if (cnt <= WTHR) {
      // ---------- wide path: node-per-block, k split by warp ----------
      for (int idx = lo + (int)blockIdx.x; idx < hi; idx += gridDim.x) {
        const int gg = g_sched[idx];
        const int pg = g_par[gg];
        const int tok = g_tok[gg], ptok = g_tok[pg];
        sm.wide.hs[t] = __ldcg(&g_hsum [gg * DIM + t]);
        sm.wide.fc[t] = __ldcg(&g_fcsum[gg * DIM + t]);
        __syncthreads();

        {
          const int k0 = w << 5;
          #pragma unroll 2
          for (int j = 0; j < 24; ++j) {
            float p = 0.f;
            const float* col = Wiouh + k0 * DIM3 + l + 32*j;
            #pragma unroll
            for (int kk = 0; kk < 32; ++kk)
              p = fmaf(sm.wide.hs[k0 + kk], __ldg(col + kk * DIM3), p);
            sm.wide.red[w][l + 32*j] = p;
          }
        }
        __syncthreads();

        float i0 = 0.f, o0 = 0.f, u0 = 0.f;
        #pragma unroll
        for (int w2 = 0; w2 < 8; ++w2) {
          i0 += sm.wide.red[w2][t];
          o0 += sm.wide.red[w2][DIM + t];
          u0 += sm.wide.red[w2][2*DIM + t];
        }
        const int tv = tok * DIM3;
        i0 += g_embp_iou[tv + t];
        o0 += g_embp_iou[tv + DIM + t];
        u0 += g_embp_iou[tv + 2*DIM + t];
        const float cval = sigm(i0) * tanhf(u0) + sm.wide.fc[t];
        const float hval = sigm(o0) * tanhf(cval);
        __syncthreads();
        sm.wide.hv[t] = hval;
        __syncthreads();

        {
          const int k0 = w << 5;
          #pragma unroll 2
          for (int j = 0; j < 8; ++j) {
            float p = 0.f;
            const float* col = Wfh + k0 * DIM + l + 32*j;
            #pragma unroll
            for (int kk = 0; kk < 32; ++kk)
              p = fmaf(sm.wide.hv[k0 + kk], __ldg(col + kk * DIM), p);
            sm.wide.red[w][l + 32*j] = p;
          }
        }
        __syncthreads();

        float f = g_embp_fx[ptok * DIM + t];
        #pragma unroll
        for (int w2 = 0; w2 < 8; ++w2) f += sm.wide.red[w2][t];

        if ((gg & (NN - 1)) == 0) {
          g_croot[(gg >> 16) * DIM + t] = cval;
        } else {
          atomicAdd(&g_hsum [pg * DIM + t], hval);
          atomicAdd(&g_fcsum[pg * DIM + t], sigm(f) * cval);
        }
        __syncthreads();
      }
    } else {
      // ---------- fat path: 16-node chunks, f32x2 (R9-measured config) ----------
      const int nch = (cnt + TB - 1) / TB;
      for (int ch = blockIdx.x; ch < nch; ch += gridDim.x) {
        const int base = lo + ch * TB;
        __syncthreads();                 // previous chunk done with shared

        if (t < TB) {
          const int gg = (base + t < hi) ? g_sched[base + t] : -1;
          snode[t] = gg;
          if (gg >= 0) {
            const int pg = g_par[gg];
            spar[t] = pg; stok[t] = g_tok[gg]; sptok[t] = g_tok[pg];
          }
        }
        __syncthreads();

        #pragma unroll
        for (int b = 0; b < TB; ++b) {
          const int gg = snode[b];
          sm.fat.hT[t][b]   = (gg >= 0) ? __ldcg(&g_hsum [gg * DIM + t]) : 0.0f;
          sm.fat.fcsh[b][t] = (gg >= 0) ? __ldcg(&g_fcsum[gg * DIM + t]) : 0.0f;
        }

        unsigned long long A0[8], A1[8], A2[8];
        #pragma unroll
        for (int p = 0; p < 8; ++p) {
          float e00 = 0.f, e01 = 0.f, e10 = 0.f, e11 = 0.f, e20 = 0.f, e21 = 0.f;
          if (snode[2*p] >= 0) {
            const int tv = stok[2*p] * DIM3;
            e00 = g_embp_iou[tv + t]; e10 = g_embp_iou[tv + DIM + t]; e20 = g_embp_iou[tv + 2*DIM + t];
          }
          if (snode[2*p+1] >= 0) {
            const int tv = stok[2*p+1] * DIM3;
            e01 = g_embp_iou[tv + t]; e11 = g_embp_iou[tv + DIM + t]; e21 = g_embp_iou[tv + 2*DIM + t];
          }
          A0[p] = pack2(e00, e01); A1[p] = pack2(e10, e11); A2[p] = pack2(e20, e21);
        }
        __syncthreads();

        // mv1: thread t owns cols t, 256+t, 512+t; FFMA2 over node pairs
        #pragma unroll 4
        for (int k = 0; k < DIM; ++k) {
          const float* wr = Wiouh + k * DIM3 + t;
          const float w0 = __ldg(wr), w1 = __ldg(wr + DIM), w2 = __ldg(wr + 2*DIM);
          const unsigned long long W0 = pack2(w0, w0), W1 = pack2(w1, w1), W2 = pack2(w2, w2);
          const ulonglong2* hr = reinterpret_cast<const ulonglong2*>(&sm.fat.hT[k][0]);
          const ulonglong2 hA = hr[0], hB = hr[1], hC = hr[2], hD = hr[3];
          FMA2(A0[0], hA.x, W0); FMA2(A1[0], hA.x, W1); FMA2(A2[0], hA.x, W2);
          FMA2(A0[1], hA.y, W0); FMA2(A1[1], hA.y, W1); FMA2(A2[1], hA.y, W2);
          FMA2(A0[2], hB.x, W0); FMA2(A1[2], hB.x, W1); FMA2(A2[2], hB.x, W2);
          FMA2(A0[3], hB.y, W0); FMA2(A1[3], hB.y, W1); FMA2(A2[3], hB.y, W2);
          FMA2(A0[4], hC.x, W0); FMA2(A1[4], hC.x, W1); FMA2(A2[4], hC.x, W2);
          FMA2(A0[5], hC.y, W0); FMA2(A1[5], hC.y, W1); FMA2(A2[5], hC.y, W2);
          FMA2(A0[6], hD.x, W0); FMA2(A1[6], hD.x, W1); FMA2(A2[6], hD.x, W2);
          FMA2(A0[7], hD.y, W0); FMA2(A1[7], hD.y, W1); FMA2(A2[7], hD.y, W2);
        }

        // gates: cc -> fcsh (same-thread overwrite), hh in regs
        float hh[TB];
        #pragma unroll
        for (int p = 0; p < 8; ++p) {
          float a0l, a0h, a1l, a1h, a2l, a2h;
          unpack2(A0[p], a0l, a0h);
          unpack2(A1[p], a1l, a1h);
          unpack2(A2[p], a2l, a2h);
          {
            const int b = 2*p;
            const float c = sigm(a0l) * tanhf(a2l) + sm.fat.fcsh[b][t];
            hh[b] = sigm(a1l) * tanhf(c);
            sm.fat.fcsh[b][t] = c;
          }
          {
            const int b = 2*p + 1;
            const float c = sigm(a0h) * tanhf(a2h) + sm.fat.fcsh[b][t];
            hh[b] = sigm(a1h) * tanhf(c);
            sm.fat.fcsh[b][t] = c;
          }
        }
        __syncthreads();
        #pragma unroll
        for (int b = 0; b < TB; ++b) sm.fat.hT[t][b] = hh[b];
        __syncthreads();

        // mv2: fpre = h @ Wfh + folded(embp_fx[parent_tok])
        unsigned long long F[8];
        #pragma unroll
        for (int p = 0; p < 8; ++p) {
          const float f0 = (snode[2*p]   >= 0) ? g_embp_fx[sptok[2*p]   * DIM + t] : 0.f;
          const float f1 = (snode[2*p+1] >= 0) ? g_embp_fx[sptok[2*p+1] * DIM + t] : 0.f;
          F[p] = pack2(f0, f1);
        }
        #pragma unroll 4
        for (int k = 0; k < DIM; ++k) {
          const float wf = __ldg(Wfh + k * DIM + t);
          const unsigned long long Wf = pack2(wf, wf);
          const ulonglong2* hr = reinterpret_cast<const ulonglong2*>(&sm.fat.hT[k][0]);
          const ulonglong2 hA = hr[0], hB = hr[1], hC = hr[2], hD = hr[3];
          FMA2(F[0], hA.x, Wf); FMA2(F[1], hA.y, Wf);
          FMA2(F[2], hB.x, Wf); FMA2(F[3], hB.y, Wf);
          FMA2(F[4], hC.x, Wf); FMA2(F[5], hC.y, Wf);
          FMA2(F[6], hD.x, Wf); FMA2(F[7], hD.y, Wf);
        }

        // epilogue: hh from hT, cc from fcsh
        #pragma unroll
        for (int p = 0; p < 8; ++p) {
          float fl, fh2;
          unpack2(F[p], fl, fh2);
          #pragma unroll
          for (int q = 0; q < 2; ++q) {
            const int b = 2*p + q;
            const int gg = snode[b];
            if (gg < 0) continue;
            const float fv = q ? fh2 : fl;
            const float hval = sm.fat.hT[t][b];
            const float cval = sm.fat.fcsh[b][t];
            if ((gg & (NN - 1)) == 0) {
              g_croot[(gg >> 16) * DIM + t] = cval;
            } else {
              atomicAdd(&g_hsum [spar[b] * DIM + t], hval);
              atomicAdd(&g_fcsum[spar[b] * DIM + t], sigm(fv) * cval);
            }
          }
        }
      }
    }
    gbar();   // level complete on the whole grid
  }
}

// ---------------- phase 5a: head matvec partials (8 blocks, k-sliced) ----------------
__global__ void k_head1(const float* __restrict__ Wh) {
  __shared__ float v[64];
  const int t = threadIdx.x, b = blockIdx.x;
  if (t < 64) {
    const int k = b * 64 + t;
    if (k < DIM) v[t] = g_croot[k] * g_croot[DIM + k];          // cl*cr
    else         v[t] = fabsf(g_croot[k - DIM] - g_croot[k]);   // |cl-cr|
  }
  __syncthreads();
  float acc = 0.f;
  const float* wp = Wh + (size_t)b * 64 * DIM + t;
  #pragma unroll 8
  for (int kk = 0; kk < 64; ++kk)
    acc = fmaf(v[kk], __ldg(wp + kk * DIM), acc);
  g_hpart[b][t] = acc;
}

// ---------------- phase 5b: head finish (reduce + sigmoid + 256x2 + softmax) ----------------
__global__ void k_head2(const float* __restrict__ bh,
                        const float* __restrict__ Wp, const float* __restrict__ bp,
                        float* __restrict__ out) {
  __shared__ float s0[DIM], s1[DIM];
  const int t = threadIdx.x;
  float acc = bh[t];
  #pragma unroll
  for (int b = 0; b < 8; ++b) acc += g_hpart[b][t];
  const float hid = sigm(acc);
  s0[t] = hid * Wp[t * 2 + 0];
  s1[t] = hid * Wp[t * 2 + 1];
  __syncthreads();
  for (int s = DIM / 2; s > 0; s >>= 1) {
    if (t < s) { s0[t] += s0[t + s]; s1[t] += s1[t + s]; }
    __syncthreads();
  }
  if (t == 0) {
    const float l0 = s0[0] + bp[0], l1 = s1[0] + bp[1];
    const float m = fmaxf(l0, l1);
    const float e0 = expf(l0 - m), e1 = expf(l1 - m);
    const float inv = 1.0f / (e0 + e1);
    out[0] = e0 * inv;
    out[1] = e1 * inv;
  }
}

// ---------------- launcher (graph-capturable) ----------------
extern "C" void kernel_launch(void* const* d_in, const int* in_sizes, int n_in,
                              void* d_out, int out_size) {
  (void)in_sizes; (void)n_in;
  const int*   l_tok = (const int*)  d_in[0];
  const int*   l_par = (const int*)  d_in[1];
  const int*   r_tok = (const int*)  d_in[2];
  const int*   r_par = (const int*)  d_in[3];
  const float* emb   = (const float*)d_in[4];
  const float* Wioux = (const float*)d_in[5];
  const float* bioux = (const float*)d_in[6];
  const float* Wiouh = (const float*)d_in[7];
  const float* biouh = (const float*)d_in[8];
  const float* Wfx   = (const float*)d_in[9];
  const float* bfx   = (const float*)d_in[10];
  const float* Wfh   = (const float*)d_in[11];
  const float* bfh   = (const float*)d_in[12];
  const float* Wh    = (const float*)d_in[13];
  const float* bh    = (const float*)d_in[14];
  const float* Wp    = (const float*)d_in[15];
  const float* bp    = (const float*)d_in[16];
  float* out = (float*)d_out;
  (void)out_size;

  void *p_hs, *p_fc, *p_cnt, *p_cur, *p_mk;
  cudaGetSymbolAddress(&p_hs,  g_hsum);
  cudaGetSymbolAddress(&p_fc,  g_fcsum);
  cudaGetSymbolAddress(&p_cnt, g_cnt);
  cudaGetSymbolAddress(&p_cur, g_cur);
  cudaGetSymbolAddress(&p_mk,  g_mark);
  cudaMemsetAsync(p_hs,  0, sizeof(float) * 2ull * NN * DIM);
  cudaMemsetAsync(p_fc,  0, sizeof(float) * 2ull * NN * DIM);
  cudaMemsetAsync(p_cnt, 0, sizeof(int) * 2 * MAXLV);
  cudaMemsetAsync(p_cur, 0, sizeof(int) * 2 * MAXLV);
  cudaMemsetAsync(p_mk,  0, sizeof(int) * 2 * NN);

  k_prep<<<EMBB + DEPB, 256>>>(emb, Wioux, bioux, biouh, Wfx, bfx, bfh, Wfh,
                               l_par, r_par, l_tok, r_tok);
  k_scan<<<1, 256>>>();
  k_scatlf<<<DEPB + (2 * NN + 3) / 4, 256>>>();

  int dev = 0;
  cudaGetDevice(&dev);
  int sms = 148;
  cudaDeviceGetAttribute(&sms, cudaDevAttrMultiProcessorCount, dev);
  int maxb = 1;
  cudaOccupancyMaxActiveBlocksPerMultiprocessor(&maxb, k_levels, 256, 0);
  if (maxb > 2) maxb = 2;
  if (maxb < 1) maxb = 1;
  k_levels<<<sms * maxb, 256>>>(Wiouh, Wfh);   // grid == guaranteed-resident blocks (gbar-safe)

  k_head1<<<8, 256>>>(Wh);
  k_head2<<<1, DIM>>>(bh, Wp, bp, out);
}